// round 13
// baseline (speedup 1.0000x reference)
#include <cuda_runtime.h>
#include <mma.h>
using namespace nvcuda;

#define N_NODES 100000
#define N_EDGES 1600000
#define IN_F    48
#define EDGE_F  32
#define HID_F   128
#define OUT_F   64
#define H0_F    96   // 2*IN_F
#define SCAN_NB 98   // ceil(N_NODES/1024)

// ---------------- scratch (static device allocations only) ----------------
__device__ int   g_deg[N_NODES];
__device__ int   g_rowptr[N_NODES + 1];
__device__ int   g_cursor[N_NODES];
__device__ int   g_bsum[128];
__device__ int   g_boff[128];
__device__ int4  g_csr[N_EDGES];           // (src, eid, dst, pad) packed
__device__ float g_hsum[N_NODES * IN_F];   // layer0 aggregated sums (pre-mean)
__device__ float g_h  [N_NODES * H0_F];    // concat(nfeat, h_neigh0)
__device__ float g_hn1[N_NODES * H0_F];    // seg_mean(h[src])
__device__ float g_h1 [N_NODES * HID_F];   // layer1 output
__device__ float g_s2z[N_NODES * 128];     // [h1@W2s+b2 | h1@W2n]

// ---------------- packed f32x2 helpers ----------------
__device__ __forceinline__ unsigned long long pack2(float lo, float hi) {
    unsigned long long u;
    asm("mov.b64 %0, {%1, %2};" : "=l"(u) : "f"(lo), "f"(hi));
    return u;
}
__device__ __forceinline__ float2 unpack2(unsigned long long u) {
    float lo, hi;
    asm("mov.b64 {%0, %1}, %2;" : "=f"(lo), "=f"(hi) : "l"(u));
    return make_float2(lo, hi);
}
__device__ __forceinline__ unsigned long long fma2(unsigned long long a,
                                                   unsigned long long b,
                                                   unsigned long long c) {
    unsigned long long d;
    asm("fma.rn.f32x2 %0, %1, %2, %3;" : "=l"(d) : "l"(a), "l"(b), "l"(c));
    return d;
}
// vector reduction: 4 floats in one red op (sm_90+)
__device__ __forceinline__ void red_add_v4(float* p, float a, float b, float c, float d) {
    asm volatile("red.global.add.v4.f32 [%0], {%1, %2, %3, %4};"
                 :: "l"(p), "f"(a), "f"(b), "f"(c), "f"(d) : "memory");
}

// ---------------- CSR build ----------------
__global__ void k_deg(const int* __restrict__ dst) {
    int i = blockIdx.x * blockDim.x + threadIdx.x;
    if (i < N_EDGES) atomicAdd(&g_deg[dst[i]], 1);
}

// parallel scan, phase 1: per-block exclusive scan + block sums
__global__ void k_scan_blocks() {
    __shared__ int wsum[32];
    int t = threadIdx.x, lane = t & 31, w = t >> 5;
    int i = blockIdx.x * 1024 + t;
    int v = (i < N_NODES) ? g_deg[i] : 0;
    int x = v;
    #pragma unroll
    for (int o = 1; o < 32; o <<= 1) {
        int y = __shfl_up_sync(0xffffffffu, x, o);
        if (lane >= o) x += y;
    }
    if (lane == 31) wsum[w] = x;
    __syncthreads();
    if (w == 0) {
        int s = wsum[lane];
        #pragma unroll
        for (int o = 1; o < 32; o <<= 1) {
            int y = __shfl_up_sync(0xffffffffu, s, o);
            if (lane >= o) s += y;
        }
        wsum[lane] = s;
    }
    __syncthreads();
    int excl = (w ? wsum[w - 1] : 0) + (x - v);
    if (i < N_NODES) g_rowptr[i] = excl;
    if (t == 0) g_bsum[blockIdx.x] = wsum[31];
}

// phase 2: one warp scans block sums
__global__ void k_scan_top() {
    int l = threadIdx.x;  // 32 threads
    int running = 0;
    for (int base = 0; base < SCAN_NB; base += 32) {
        int v = (base + l < SCAN_NB) ? g_bsum[base + l] : 0;
        int x = v;
        #pragma unroll
        for (int o = 1; o < 32; o <<= 1) {
            int y = __shfl_up_sync(0xffffffffu, x, o);
            if (l >= o) x += y;
        }
        if (base + l < SCAN_NB) g_boff[base + l] = running + x - v;
        running += __shfl_sync(0xffffffffu, x, 31);
    }
    if (l == 0) g_rowptr[N_NODES] = running;
}

// phase 3: add block offsets, init cursor
__global__ void k_scan_add() {
    int i = blockIdx.x * blockDim.x + threadIdx.x;
    if (i < N_NODES) {
        int rp = g_rowptr[i] + g_boff[i >> 10];
        g_rowptr[i] = rp;
        g_cursor[i] = rp;
    }
}

__global__ void k_fill(const int* __restrict__ src, const int* __restrict__ dst) {
    int i = blockIdx.x * blockDim.x + threadIdx.x;
    if (i < N_EDGES) {
        int d = dst[i];
        int p = atomicAdd(&g_cursor[d], 1);
        g_csr[p] = make_int4(src[i], i, d, 0);
    }
}

// ---------------- layer0: pipelined register-tiled edge GEMM + segment reduce ----
#define L0_TILE    128
#define L0_THREADS 384

__global__ void __launch_bounds__(L0_THREADS, 2) k_layer0_gemm(
    const float* __restrict__ nfeat, const float* __restrict__ efeat,
    const float* __restrict__ We, const float* __restrict__ be)
{
    __shared__ float AsT[2][EDGE_F][L0_TILE]; // k-major efeat tiles, XOR swizzled
    __shared__ float Bs[EDGE_F][IN_F];        // 32x48 weights
    __shared__ float bes[IN_F];
    __shared__ int   srcs_s[2 * L0_TILE];
    __shared__ int   dsts_s[2 * L0_TILE];
    __shared__ int   eids_s[2 * L0_TILE];

    const int t  = threadIdx.x;
    const int j0 = blockIdx.x * 2 * L0_TILE;

    if (t < 2 * L0_TILE) {
        int4 v = g_csr[j0 + t];
        srcs_s[t] = v.x;
        eids_s[t] = v.y;
        dsts_s[t] = v.z;
    }
    if (t < 384) {  // weights: 32x48 floats = 384 float4s
        int r = t / 12, c4 = t % 12;
        *(float4*)&Bs[r][c4 * 4] = *(const float4*)&We[r * IN_F + c4 * 4];
    }
    if (t < IN_F) bes[t] = be[t];
    __syncthreads();

    float4 pre[3];
    #pragma unroll
    for (int i = 0; i < 3; i++) {
        int idx = t + i * L0_THREADS;
        if (idx < L0_TILE * 8) {
            int row = idx >> 3, c4 = idx & 7;
            pre[i] = *(const float4*)&efeat[(size_t)eids_s[row] * EDGE_F + c4 * 4];
        }
    }
    #pragma unroll
    for (int i = 0; i < 3; i++) {
        int idx = t + i * L0_THREADS;
        if (idx < L0_TILE * 8) {
            int row = idx >> 3, c4 = idx & 7;
            int pos = row ^ (8 * (c4 & 3));
            AsT[0][4 * c4 + 0][pos] = pre[i].x;
            AsT[0][4 * c4 + 1][pos] = pre[i].y;
            AsT[0][4 * c4 + 2][pos] = pre[i].z;
            AsT[0][4 * c4 + 3][pos] = pre[i].w;
        }
    }
    #pragma unroll
    for (int i = 0; i < 3; i++) {
        int idx = t + i * L0_THREADS;
        if (idx < L0_TILE * 8) {
            int row = idx >> 3, c4 = idx & 7;
            pre[i] = *(const float4*)&efeat[(size_t)eids_s[L0_TILE + row] * EDGE_F + c4 * 4];
        }
    }
    __syncthreads();

    const int rt = t & 31;          // row tile 0..31 (4 rows each)
    const int ct = t >> 5;          // col tile 0..11 (4 cols each)
    const int r0 = rt * 4, c0 = ct * 4;

    const unsigned long long bias0 = pack2(bes[c0 + 0], bes[c0 + 1]);
    const unsigned long long bias1 = pack2(bes[c0 + 2], bes[c0 + 3]);

    #pragma unroll
    for (int tile = 0; tile < 2; tile++) {
        if (tile == 1) {
            #pragma unroll
            for (int i = 0; i < 3; i++) {
                int idx = t + i * L0_THREADS;
                if (idx < L0_TILE * 8) {
                    int row = idx >> 3, c4 = idx & 7;
                    int pos = row ^ (8 * (c4 & 3));
                    AsT[1][4 * c4 + 0][pos] = pre[i].x;
                    AsT[1][4 * c4 + 1][pos] = pre[i].y;
                    AsT[1][4 * c4 + 2][pos] = pre[i].z;
                    AsT[1][4 * c4 + 3][pos] = pre[i].w;
                }
            }
            __syncthreads();
        }
        const int base = tile * L0_TILE;

        unsigned long long acc2[4][2];
        #pragma unroll
        for (int m = 0; m < 4; m++) { acc2[m][0] = bias0; acc2[m][1] = bias1; }

        #pragma unroll 8
        for (int k = 0; k < EDGE_F; k++) {
            int rs = r0 ^ (8 * ((k >> 2) & 3));
            float4 av = *(const float4*)&AsT[tile][k][rs];
            ulonglong2 bA = *(const ulonglong2*)&Bs[k][c0];
            unsigned long long bb0 = bA.x, bb1 = bA.y;
            float a[4] = {av.x, av.y, av.z, av.w};
            #pragma unroll
            for (int m = 0; m < 4; m++) {
                unsigned long long am = pack2(a[m], a[m]);
                acc2[m][0] = fma2(am, bb0, acc2[m][0]);
                acc2[m][1] = fma2(am, bb1, acc2[m][1]);
            }
        }

        float4 nf[4];
        #pragma unroll
        for (int i = 0; i < 4; i++)
            nf[i] = *(const float4*)&nfeat[(size_t)srcs_s[base + r0 + i] * IN_F + c0];

        float s0 = 0.f, s1 = 0.f, s2 = 0.f, s3 = 0.f;
        int cur = dsts_s[base + r0];
        #pragma unroll
        for (int i = 0; i < 4; i++) {
            int d = dsts_s[base + r0 + i];
            if (d != cur) {
                red_add_v4(&g_hsum[(size_t)cur * IN_F + c0], s0, s1, s2, s3);
                s0 = s1 = s2 = s3 = 0.f;
                cur = d;
            }
            float2 e0 = unpack2(acc2[i][0]);
            float2 e1 = unpack2(acc2[i][1]);
            s0 = fmaf(fmaxf(e0.x, 0.f), nf[i].x, s0);
            s1 = fmaf(fmaxf(e0.y, 0.f), nf[i].y, s1);
            s2 = fmaf(fmaxf(e1.x, 0.f), nf[i].z, s2);
            s3 = fmaf(fmaxf(e1.y, 0.f), nf[i].w, s3);
        }
        red_add_v4(&g_hsum[(size_t)cur * IN_F + c0], s0, s1, s2, s3);
    }
}

// divide by degree + build concat h = [nfeat | mean]
__global__ void k_finalize0(const float* __restrict__ nfeat) {
    int i = blockIdx.x * blockDim.x + threadIdx.x;
    if (i >= N_NODES * IN_F) return;
    int n = i / IN_F, c = i % IN_F;
    int deg = g_rowptr[n + 1] - g_rowptr[n];
    float inv = 1.f / fmaxf((float)deg, 1.f);
    g_h[n * H0_F + c]        = nfeat[i];
    g_h[n * H0_F + IN_F + c] = g_hsum[i] * inv;
}

// ---------------- mean96: warp per node, float4 lanes (24 active) ----------------
__global__ void __launch_bounds__(256) k_mean96() {
    int gw = (blockIdx.x * blockDim.x + threadIdx.x) >> 5;
    int l  = threadIdx.x & 31;
    if (gw >= N_NODES || l >= 24) return;
    int beg = g_rowptr[gw], end = g_rowptr[gw + 1];
    float4 A = make_float4(0.f, 0.f, 0.f, 0.f);
    float4 B = make_float4(0.f, 0.f, 0.f, 0.f);
    int j = beg;
    for (; j + 2 <= end; j += 2) {
        float4 va = ((const float4*)&g_h[(size_t)g_csr[j].x     * H0_F])[l];
        float4 vb = ((const float4*)&g_h[(size_t)g_csr[j + 1].x * H0_F])[l];
        A.x += va.x; A.y += va.y; A.z += va.z; A.w += va.w;
        B.x += vb.x; B.y += vb.y; B.z += vb.z; B.w += vb.w;
    }
    if (j < end) {
        float4 va = ((const float4*)&g_h[(size_t)g_csr[j].x * H0_F])[l];
        A.x += va.x; A.y += va.y; A.z += va.z; A.w += va.w;
    }
    float inv = 1.f / fmaxf((float)(end - beg), 1.f);
    float4 r;
    r.x = (A.x + B.x) * inv; r.y = (A.y + B.y) * inv;
    r.z = (A.z + B.z) * inv; r.w = (A.w + B.w) * inv;
    ((float4*)&g_hn1[(size_t)gw * H0_F])[l] = r;
}

// ---------------- GEMM1 (TF32 wmma): g_h1 = relu(g_h@W1s + g_hn1@W1n + b1) ----
// 256 threads = 8 warps in 2(m) x 4(n); warp tile 64x32 of 16x16x8 tf32 frags.
__global__ void __launch_bounds__(256) k_gemm1(
    const float* __restrict__ Wa, const float* __restrict__ Wb,
    const float* __restrict__ bias)
{
    constexpr int BM = 128, BK = 32, APAD = 36, BPAD = 132;
    __shared__ float As[BM][APAD];
    __shared__ float Bs[BK][BPAD];
    __shared__ float Cs[8][16][20];

    int t = threadIdx.x, warp = t >> 5, lane = t & 31;
    int wm = warp & 1, wn = warp >> 1;
    int brow = blockIdx.x * BM;

    wmma::fragment<wmma::accumulator, 16, 16, 8, float> acc[4][2];
    #pragma unroll
    for (int i = 0; i < 4; i++)
        #pragma unroll
        for (int j = 0; j < 2; j++) wmma::fill_fragment(acc[i][j], 0.f);

    #pragma unroll
    for (int phase = 0; phase < 2; phase++) {
        const float* A = phase ? g_hn1 : g_h;
        const float* W = phase ? Wb : Wa;
        for (int kt = 0; kt < H0_F; kt += BK) {
            #pragma unroll
            for (int i = 0; i < 4; i++) {
                int idx = t + i * 256;
                int r = idx >> 3, c4 = idx & 7;
                int grow = brow + r;
                float4 v = make_float4(0.f, 0.f, 0.f, 0.f);
                if (grow < N_NODES)
                    v = *(const float4*)&A[(size_t)grow * H0_F + kt + c4 * 4];
                As[r][c4 * 4 + 0] = wmma::__float_to_tf32(v.x);
                As[r][c4 * 4 + 1] = wmma::__float_to_tf32(v.y);
                As[r][c4 * 4 + 2] = wmma::__float_to_tf32(v.z);
                As[r][c4 * 4 + 3] = wmma::__float_to_tf32(v.w);
            }
            #pragma unroll
            for (int i = 0; i < 4; i++) {
                int idx = t + i * 256;
                int r = idx >> 5, c4 = idx & 31;
                float4 v = *(const float4*)&W[(size_t)(kt + r) * HID_F + c4 * 4];
                Bs[r][c4 * 4 + 0] = wmma::__float_to_tf32(v.x);
                Bs[r][c4 * 4 + 1] = wmma::__float_to_tf32(v.y);
                Bs[r][c4 * 4 + 2] = wmma::__float_to_tf32(v.z);
                Bs[r][c4 * 4 + 3] = wmma::__float_to_tf32(v.w);
            }
            __syncthreads();
            #pragma unroll
            for (int kk = 0; kk < 4; kk++) {
                wmma::fragment<wmma::matrix_a, 16, 16, 8, wmma::precision::tf32, wmma::row_major> af[4];
                #pragma unroll
                for (int i = 0; i < 4; i++)
                    wmma::load_matrix_sync(af[i], &As[wm * 64 + i * 16][kk * 8], APAD);
                wmma::fragment<wmma::matrix_b, 16, 16, 8, wmma::precision::tf32, wmma::row_major> bf[2];
                #pragma unroll
                for (int j = 0; j < 2; j++)
                    wmma::load_matrix_sync(bf[j], &Bs[kk * 8][wn * 32 + j * 16], BPAD);
                #pragma unroll
                for (int i = 0; i < 4; i++)
                    #pragma unroll
                    for (int j = 0; j < 2; j++)
                        wmma::mma_sync(acc[i][j], af[i], bf[j], acc[i][j]);
            }
            __syncthreads();
        }
    }
    // epilogue: per-warp smem patch, bias + relu
    #pragma unroll
    for (int i = 0; i < 4; i++) {
        #pragma unroll
        for (int j = 0; j < 2; j++) {
            wmma::store_matrix_sync(&Cs[warp][0][0], acc[i][j], 20, wmma::mem_row_major);
            __syncwarp();
            #pragma unroll
            for (int e = 0; e < 8; e++) {
                int idx = lane * 8 + e;
                int r = idx >> 4, c = idx & 15;
                int grow = brow + wm * 64 + i * 16 + r;
                int col = wn * 32 + j * 16 + c;
                if (grow < N_NODES) {
                    float v = Cs[warp][r][c] + bias[col];
                    g_h1[(size_t)grow * HID_F + col] = fmaxf(v, 0.f);
                }
            }
            __syncwarp();
        }
    }
}

// ---------------- GEMM2 (TF32 wmma): g_s2z = [h1@W2s + b2 | h1@W2n] ----------------
__global__ void __launch_bounds__(256) k_gemm2(
    const float* __restrict__ Wa, const float* __restrict__ Wb,
    const float* __restrict__ bias)
{
    constexpr int BM = 128, BK = 32, APAD = 36, BPAD = 132;
    __shared__ float As[BM][APAD];
    __shared__ float Bs[BK][BPAD];
    __shared__ float Cs[8][16][20];

    int t = threadIdx.x, warp = t >> 5, lane = t & 31;
    int wm = warp & 1, wn = warp >> 1;
    int brow = blockIdx.x * BM;

    wmma::fragment<wmma::accumulator, 16, 16, 8, float> acc[4][2];
    #pragma unroll
    for (int i = 0; i < 4; i++)
        #pragma unroll
        for (int j = 0; j < 2; j++) wmma::fill_fragment(acc[i][j], 0.f);

    for (int kt = 0; kt < HID_F; kt += BK) {
        #pragma unroll
        for (int i = 0; i < 4; i++) {
            int idx = t + i * 256;
            int r = idx >> 3, c4 = idx & 7;
            int grow = brow + r;
            float4 v = make_float4(0.f, 0.f, 0.f, 0.f);
            if (grow < N_NODES)
                v = *(const float4*)&g_h1[(size_t)grow * HID_F + kt + c4 * 4];
            As[r][c4 * 4 + 0] = wmma::__float_to_tf32(v.x);
            As[r][c4 * 4 + 1] = wmma::__float_to_tf32(v.y);
            As[r][c4 * 4 + 2] = wmma::__float_to_tf32(v.z);
            As[r][c4 * 4 + 3] = wmma::__float_to_tf32(v.w);
        }
        #pragma unroll
        for (int i = 0; i < 4; i++) {
            int idx = t + i * 256;
            int r = idx >> 5, c4 = idx & 31;
            float4 v;
            if (c4 < 16) v = *(const float4*)&Wa[(size_t)(kt + r) * OUT_F + c4 * 4];
            else         v = *(const float4*)&Wb[(size_t)(kt + r) * OUT_F + (c4 - 16) * 4];
            Bs[r][c4 * 4 + 0] = wmma::__float_to_tf32(v.x);
            Bs[r][c4 * 4 + 1] = wmma::__float_to_tf32(v.y);
            Bs[r][c4 * 4 + 2] = wmma::__float_to_tf32(v.z);
            Bs[r][c4 * 4 + 3] = wmma::__float_to_tf32(v.w);
        }
        __syncthreads();
        #pragma unroll
        for (int kk = 0; kk < 4; kk++) {
            wmma::fragment<wmma::matrix_a, 16, 16, 8, wmma::precision::tf32, wmma::row_major> af[4];
            #pragma unroll
            for (int i = 0; i < 4; i++)
                wmma::load_matrix_sync(af[i], &As[wm * 64 + i * 16][kk * 8], APAD);
            wmma::fragment<wmma::matrix_b, 16, 16, 8, wmma::precision::tf32, wmma::row_major> bf[2];
            #pragma unroll
            for (int j = 0; j < 2; j++)
                wmma::load_matrix_sync(bf[j], &Bs[kk * 8][wn * 32 + j * 16], BPAD);
            #pragma unroll
            for (int i = 0; i < 4; i++)
                #pragma unroll
                for (int j = 0; j < 2; j++)
                    wmma::mma_sync(acc[i][j], af[i], bf[j], acc[i][j]);
        }
        __syncthreads();
    }
    // epilogue: bias only on cols < OUT_F, no relu
    #pragma unroll
    for (int i = 0; i < 4; i++) {
        #pragma unroll
        for (int j = 0; j < 2; j++) {
            wmma::store_matrix_sync(&Cs[warp][0][0], acc[i][j], 20, wmma::mem_row_major);
            __syncwarp();
            #pragma unroll
            for (int e = 0; e < 8; e++) {
                int idx = lane * 8 + e;
                int r = idx >> 4, c = idx & 15;
                int grow = brow + wm * 64 + i * 16 + r;
                int col = wn * 32 + j * 16 + c;
                if (grow < N_NODES) {
                    float v = Cs[warp][r][c] + (col < OUT_F ? bias[col] : 0.f);
                    g_s2z[(size_t)grow * 128 + col] = v;
                }
            }
            __syncwarp();
        }
    }
}

// ---------------- final: out = S2 + seg_mean(Z[src]); half-warp per node ----------------
__global__ void __launch_bounds__(256) k_final(float* __restrict__ out) {
    int gt  = blockIdx.x * blockDim.x + threadIdx.x;
    int ghw = gt >> 4;            // half-warp id = node
    int hl  = gt & 15;            // 16 lanes x float4 = 64 cols
    if (ghw >= N_NODES) return;
    int beg = g_rowptr[ghw], end = g_rowptr[ghw + 1];
    float4 A = make_float4(0.f, 0.f, 0.f, 0.f);
    float4 B = make_float4(0.f, 0.f, 0.f, 0.f);
    int j = beg;
    for (; j + 2 <= end; j += 2) {
        float4 va = ((const float4*)&g_s2z[(size_t)g_csr[j].x     * 128 + OUT_F])[hl];
        float4 vb = ((const float4*)&g_s2z[(size_t)g_csr[j + 1].x * 128 + OUT_F])[hl];
        A.x += va.x; A.y += va.y; A.z += va.z; A.w += va.w;
        B.x += vb.x; B.y += vb.y; B.z += vb.z; B.w += vb.w;
    }
    if (j < end) {
        float4 va = ((const float4*)&g_s2z[(size_t)g_csr[j].x * 128 + OUT_F])[hl];
        A.x += va.x; A.y += va.y; A.z += va.z; A.w += va.w;
    }
    float inv = 1.f / fmaxf((float)(end - beg), 1.f);
    float4 s2 = ((const float4*)&g_s2z[(size_t)ghw * 128])[hl];
    float4 r;
    r.x = s2.x + (A.x + B.x) * inv;
    r.y = s2.y + (A.y + B.y) * inv;
    r.z = s2.z + (A.z + B.z) * inv;
    r.w = s2.w + (A.w + B.w) * inv;
    ((float4*)&out[(size_t)ghw * OUT_F])[hl] = r;
}

// ---------------- launch ----------------
extern "C" void kernel_launch(void* const* d_in, const int* in_sizes, int n_in,
                              void* d_out, int out_size)
{
    const float* nfeat = (const float*)d_in[0];
    const float* efeat = (const float*)d_in[1];
    const int*   src   = (const int*)d_in[2];
    const int*   dst   = (const int*)d_in[3];
    const float* We    = (const float*)d_in[4];
    const float* be    = (const float*)d_in[5];
    const float* W1s   = (const float*)d_in[6];
    const float* W1n   = (const float*)d_in[7];
    const float* b1    = (const float*)d_in[8];
    const float* W2s   = (const float*)d_in[9];
    const float* W2n   = (const float*)d_in[10];
    const float* b2    = (const float*)d_in[11];
    float* out = (float*)d_out;

    const int WARP_GRID = (N_NODES * 32 + 255) / 256;   // warp-per-node kernels
    const int HW_GRID   = (N_NODES * 16 + 255) / 256;   // half-warp-per-node

    void* p = nullptr;
    cudaGetSymbolAddress(&p, g_deg);
    cudaMemsetAsync(p, 0, N_NODES * sizeof(int));
    cudaGetSymbolAddress(&p, g_hsum);
    cudaMemsetAsync(p, 0, (size_t)N_NODES * IN_F * sizeof(float));

    k_deg<<<(N_EDGES + 255) / 256, 256>>>(dst);
    k_scan_blocks<<<SCAN_NB, 1024>>>();
    k_scan_top<<<1, 32>>>();
    k_scan_add<<<SCAN_NB, 1024>>>();
    k_fill<<<(N_EDGES + 255) / 256, 256>>>(src, dst);
    k_layer0_gemm<<<N_EDGES / (2 * L0_TILE), L0_THREADS>>>(nfeat, efeat, We, be);
    k_finalize0<<<(N_NODES * IN_F + 255) / 256, 256>>>(nfeat);
    k_mean96<<<WARP_GRID, 256>>>();
    k_gemm1<<<(N_NODES + 127) / 128, 256>>>(W1s, W1n, b1);
    k_gemm2<<<(N_NODES + 127) / 128, 256>>>(W2s, W2n, b2);
    k_final<<<HW_GRID, 256>>>(out);
}

// round 16
// speedup vs baseline: 1.2109x; 1.2109x over previous
#include <cuda_runtime.h>
#include <mma.h>
using namespace nvcuda;

#define N_NODES 100000
#define N_EDGES 1600000
#define IN_F    48
#define EDGE_F  32
#define HID_F   128
#define OUT_F   64
#define H0_F    96   // 2*IN_F
#define SCAN_NB 98   // ceil(N_NODES/1024)

// ---------------- scratch (static device allocations only) ----------------
__device__ int   g_deg[N_NODES];
__device__ int   g_rowptr[N_NODES + 1];
__device__ int   g_cursor[N_NODES];
__device__ int   g_bsum[128];
__device__ int   g_boff[128];
__device__ int4  g_csr[N_EDGES];           // (src, eid, dst, pad) packed
__device__ float g_hsum[N_NODES * IN_F];   // layer0 aggregated sums (pre-mean)
__device__ float g_h  [N_NODES * H0_F];    // concat(nfeat, h_neigh0)
__device__ float g_hn1[N_NODES * H0_F];    // seg_mean(h[src])
__device__ float g_h1 [N_NODES * HID_F];   // layer1 output
__device__ float g_s2z[N_NODES * 128];     // [h1@W2s+b2 | h1@W2n]

// ---------------- packed f32x2 helpers ----------------
__device__ __forceinline__ unsigned long long pack2(float lo, float hi) {
    unsigned long long u;
    asm("mov.b64 %0, {%1, %2};" : "=l"(u) : "f"(lo), "f"(hi));
    return u;
}
__device__ __forceinline__ float2 unpack2(unsigned long long u) {
    float lo, hi;
    asm("mov.b64 {%0, %1}, %2;" : "=f"(lo), "=f"(hi) : "l"(u));
    return make_float2(lo, hi);
}
__device__ __forceinline__ unsigned long long fma2(unsigned long long a,
                                                   unsigned long long b,
                                                   unsigned long long c) {
    unsigned long long d;
    asm("fma.rn.f32x2 %0, %1, %2, %3;" : "=l"(d) : "l"(a), "l"(b), "l"(c));
    return d;
}
// vector reduction: 4 floats in one red op (sm_90+)
__device__ __forceinline__ void red_add_v4(float* p, float a, float b, float c, float d) {
    asm volatile("red.global.add.v4.f32 [%0], {%1, %2, %3, %4};"
                 :: "l"(p), "f"(a), "f"(b), "f"(c), "f"(d) : "memory");
}

// ---------------- CSR build ----------------
__global__ void k_deg(const int* __restrict__ dst) {
    int i = blockIdx.x * blockDim.x + threadIdx.x;
    if (i < N_EDGES) atomicAdd(&g_deg[dst[i]], 1);
}

// parallel scan, phase 1: per-block exclusive scan + block sums
__global__ void k_scan_blocks() {
    __shared__ int wsum[32];
    int t = threadIdx.x, lane = t & 31, w = t >> 5;
    int i = blockIdx.x * 1024 + t;
    int v = (i < N_NODES) ? g_deg[i] : 0;
    int x = v;
    #pragma unroll
    for (int o = 1; o < 32; o <<= 1) {
        int y = __shfl_up_sync(0xffffffffu, x, o);
        if (lane >= o) x += y;
    }
    if (lane == 31) wsum[w] = x;
    __syncthreads();
    if (w == 0) {
        int s = wsum[lane];
        #pragma unroll
        for (int o = 1; o < 32; o <<= 1) {
            int y = __shfl_up_sync(0xffffffffu, s, o);
            if (lane >= o) s += y;
        }
        wsum[lane] = s;
    }
    __syncthreads();
    int excl = (w ? wsum[w - 1] : 0) + (x - v);
    if (i < N_NODES) g_rowptr[i] = excl;
    if (t == 0) g_bsum[blockIdx.x] = wsum[31];
}

// phase 2: one warp scans block sums
__global__ void k_scan_top() {
    int l = threadIdx.x;  // 32 threads
    int running = 0;
    for (int base = 0; base < SCAN_NB; base += 32) {
        int v = (base + l < SCAN_NB) ? g_bsum[base + l] : 0;
        int x = v;
        #pragma unroll
        for (int o = 1; o < 32; o <<= 1) {
            int y = __shfl_up_sync(0xffffffffu, x, o);
            if (l >= o) x += y;
        }
        if (base + l < SCAN_NB) g_boff[base + l] = running + x - v;
        running += __shfl_sync(0xffffffffu, x, 31);
    }
    if (l == 0) g_rowptr[N_NODES] = running;
}

// phase 3: add block offsets, init cursor
__global__ void k_scan_add() {
    int i = blockIdx.x * blockDim.x + threadIdx.x;
    if (i < N_NODES) {
        int rp = g_rowptr[i] + g_boff[i >> 10];
        g_rowptr[i] = rp;
        g_cursor[i] = rp;
    }
}

__global__ void k_fill(const int* __restrict__ src, const int* __restrict__ dst) {
    int i = blockIdx.x * blockDim.x + threadIdx.x;
    if (i < N_EDGES) {
        int d = dst[i];
        int p = atomicAdd(&g_cursor[d], 1);
        g_csr[p] = make_int4(src[i], i, d, 0);
    }
}

// ---------------- layer0: pipelined register-tiled edge GEMM + segment reduce ----
#define L0_TILE    128
#define L0_THREADS 384

__global__ void __launch_bounds__(L0_THREADS, 2) k_layer0_gemm(
    const float* __restrict__ nfeat, const float* __restrict__ efeat,
    const float* __restrict__ We, const float* __restrict__ be)
{
    __shared__ float AsT[2][EDGE_F][L0_TILE]; // k-major efeat tiles, XOR swizzled
    __shared__ float Bs[EDGE_F][IN_F];        // 32x48 weights
    __shared__ float bes[IN_F];
    __shared__ int   srcs_s[2 * L0_TILE];
    __shared__ int   dsts_s[2 * L0_TILE];
    __shared__ int   eids_s[2 * L0_TILE];

    const int t  = threadIdx.x;
    const int j0 = blockIdx.x * 2 * L0_TILE;

    if (t < 2 * L0_TILE) {
        int4 v = g_csr[j0 + t];
        srcs_s[t] = v.x;
        eids_s[t] = v.y;
        dsts_s[t] = v.z;
    }
    if (t < 384) {  // weights: 32x48 floats = 384 float4s
        int r = t / 12, c4 = t % 12;
        *(float4*)&Bs[r][c4 * 4] = *(const float4*)&We[r * IN_F + c4 * 4];
    }
    if (t < IN_F) bes[t] = be[t];
    __syncthreads();

    float4 pre[3];
    #pragma unroll
    for (int i = 0; i < 3; i++) {
        int idx = t + i * L0_THREADS;
        if (idx < L0_TILE * 8) {
            int row = idx >> 3, c4 = idx & 7;
            pre[i] = *(const float4*)&efeat[(size_t)eids_s[row] * EDGE_F + c4 * 4];
        }
    }
    #pragma unroll
    for (int i = 0; i < 3; i++) {
        int idx = t + i * L0_THREADS;
        if (idx < L0_TILE * 8) {
            int row = idx >> 3, c4 = idx & 7;
            int pos = row ^ (8 * (c4 & 3));
            AsT[0][4 * c4 + 0][pos] = pre[i].x;
            AsT[0][4 * c4 + 1][pos] = pre[i].y;
            AsT[0][4 * c4 + 2][pos] = pre[i].z;
            AsT[0][4 * c4 + 3][pos] = pre[i].w;
        }
    }
    #pragma unroll
    for (int i = 0; i < 3; i++) {
        int idx = t + i * L0_THREADS;
        if (idx < L0_TILE * 8) {
            int row = idx >> 3, c4 = idx & 7;
            pre[i] = *(const float4*)&efeat[(size_t)eids_s[L0_TILE + row] * EDGE_F + c4 * 4];
        }
    }
    __syncthreads();

    const int rt = t & 31;          // row tile 0..31 (4 rows each)
    const int ct = t >> 5;          // col tile 0..11 (4 cols each)
    const int r0 = rt * 4, c0 = ct * 4;

    const unsigned long long bias0 = pack2(bes[c0 + 0], bes[c0 + 1]);
    const unsigned long long bias1 = pack2(bes[c0 + 2], bes[c0 + 3]);

    #pragma unroll
    for (int tile = 0; tile < 2; tile++) {
        if (tile == 1) {
            #pragma unroll
            for (int i = 0; i < 3; i++) {
                int idx = t + i * L0_THREADS;
                if (idx < L0_TILE * 8) {
                    int row = idx >> 3, c4 = idx & 7;
                    int pos = row ^ (8 * (c4 & 3));
                    AsT[1][4 * c4 + 0][pos] = pre[i].x;
                    AsT[1][4 * c4 + 1][pos] = pre[i].y;
                    AsT[1][4 * c4 + 2][pos] = pre[i].z;
                    AsT[1][4 * c4 + 3][pos] = pre[i].w;
                }
            }
            __syncthreads();
        }
        const int base = tile * L0_TILE;

        unsigned long long acc2[4][2];
        #pragma unroll
        for (int m = 0; m < 4; m++) { acc2[m][0] = bias0; acc2[m][1] = bias1; }

        #pragma unroll 8
        for (int k = 0; k < EDGE_F; k++) {
            int rs = r0 ^ (8 * ((k >> 2) & 3));
            float4 av = *(const float4*)&AsT[tile][k][rs];
            ulonglong2 bA = *(const ulonglong2*)&Bs[k][c0];
            unsigned long long bb0 = bA.x, bb1 = bA.y;
            float a[4] = {av.x, av.y, av.z, av.w};
            #pragma unroll
            for (int m = 0; m < 4; m++) {
                unsigned long long am = pack2(a[m], a[m]);
                acc2[m][0] = fma2(am, bb0, acc2[m][0]);
                acc2[m][1] = fma2(am, bb1, acc2[m][1]);
            }
        }

        float4 nf[4];
        #pragma unroll
        for (int i = 0; i < 4; i++)
            nf[i] = *(const float4*)&nfeat[(size_t)srcs_s[base + r0 + i] * IN_F + c0];

        float s0 = 0.f, s1 = 0.f, s2 = 0.f, s3 = 0.f;
        int cur = dsts_s[base + r0];
        #pragma unroll
        for (int i = 0; i < 4; i++) {
            int d = dsts_s[base + r0 + i];
            if (d != cur) {
                red_add_v4(&g_hsum[(size_t)cur * IN_F + c0], s0, s1, s2, s3);
                s0 = s1 = s2 = s3 = 0.f;
                cur = d;
            }
            float2 e0 = unpack2(acc2[i][0]);
            float2 e1 = unpack2(acc2[i][1]);
            s0 = fmaf(fmaxf(e0.x, 0.f), nf[i].x, s0);
            s1 = fmaf(fmaxf(e0.y, 0.f), nf[i].y, s1);
            s2 = fmaf(fmaxf(e1.x, 0.f), nf[i].z, s2);
            s3 = fmaf(fmaxf(e1.y, 0.f), nf[i].w, s3);
        }
        red_add_v4(&g_hsum[(size_t)cur * IN_F + c0], s0, s1, s2, s3);
    }
}

// divide by degree + build concat h = [nfeat | mean]
__global__ void k_finalize0(const float* __restrict__ nfeat) {
    int i = blockIdx.x * blockDim.x + threadIdx.x;
    if (i >= N_NODES * IN_F) return;
    int n = i / IN_F, c = i % IN_F;
    int deg = g_rowptr[n + 1] - g_rowptr[n];
    float inv = 1.f / fmaxf((float)deg, 1.f);
    g_h[n * H0_F + c]        = nfeat[i];
    g_h[n * H0_F + IN_F + c] = g_hsum[i] * inv;
}

// ---------------- mean96: warp per node, float4 lanes (24 active) ----------------
__global__ void __launch_bounds__(256) k_mean96() {
    int gw = (blockIdx.x * blockDim.x + threadIdx.x) >> 5;
    int l  = threadIdx.x & 31;
    if (gw >= N_NODES || l >= 24) return;
    int beg = g_rowptr[gw], end = g_rowptr[gw + 1];
    float4 A = make_float4(0.f, 0.f, 0.f, 0.f);
    float4 B = make_float4(0.f, 0.f, 0.f, 0.f);
    int j = beg;
    for (; j + 2 <= end; j += 2) {
        float4 va = ((const float4*)&g_h[(size_t)g_csr[j].x     * H0_F])[l];
        float4 vb = ((const float4*)&g_h[(size_t)g_csr[j + 1].x * H0_F])[l];
        A.x += va.x; A.y += va.y; A.z += va.z; A.w += va.w;
        B.x += vb.x; B.y += vb.y; B.z += vb.z; B.w += vb.w;
    }
    if (j < end) {
        float4 va = ((const float4*)&g_h[(size_t)g_csr[j].x * H0_F])[l];
        A.x += va.x; A.y += va.y; A.z += va.z; A.w += va.w;
    }
    float inv = 1.f / fmaxf((float)(end - beg), 1.f);
    float4 r;
    r.x = (A.x + B.x) * inv; r.y = (A.y + B.y) * inv;
    r.z = (A.z + B.z) * inv; r.w = (A.w + B.w) * inv;
    ((float4*)&g_hn1[(size_t)gw * H0_F])[l] = r;
}

// ---------------- GEMM1 (TF32 wmma): g_h1 = relu(g_h@W1s + g_hn1@W1n + b1) ----
// 256 threads = 8 warps in 2(m) x 4(n); warp tile 64x32 of 16x16x8 tf32 frags.
// Epilogue: overlay full-width C on As/Bs smem, coalesced float4 stores.
#define GA_PAD 36
#define GB_PAD 132
#define G_SMEM_BYTES (128 * GA_PAD * 4 + 32 * GB_PAD * 4)   // 35328

__global__ void __launch_bounds__(256) k_gemm1(
    const float* __restrict__ Wa, const float* __restrict__ Wb,
    const float* __restrict__ bias)
{
    __shared__ __align__(16) char smem_raw[G_SMEM_BYTES];
    float (*As)[GA_PAD] = (float(*)[GA_PAD])smem_raw;
    float (*Bs)[GB_PAD] = (float(*)[GB_PAD])(smem_raw + 128 * GA_PAD * 4);
    float (*Cs)[GB_PAD] = (float(*)[GB_PAD])smem_raw;   // overlay after mainloop

    int t = threadIdx.x, warp = t >> 5;
    int wm = warp & 1, wn = warp >> 1;
    int brow = blockIdx.x * 128;

    wmma::fragment<wmma::accumulator, 16, 16, 8, float> acc[4][2];
    #pragma unroll
    for (int i = 0; i < 4; i++)
        #pragma unroll
        for (int j = 0; j < 2; j++) wmma::fill_fragment(acc[i][j], 0.f);

    #pragma unroll
    for (int phase = 0; phase < 2; phase++) {
        const float* A = phase ? g_hn1 : g_h;
        const float* W = phase ? Wb : Wa;
        for (int kt = 0; kt < H0_F; kt += 32) {
            #pragma unroll
            for (int i = 0; i < 4; i++) {
                int idx = t + i * 256;
                int r = idx >> 3, c4 = idx & 7;
                int grow = brow + r;
                float4 v = make_float4(0.f, 0.f, 0.f, 0.f);
                if (grow < N_NODES)
                    v = *(const float4*)&A[(size_t)grow * H0_F + kt + c4 * 4];
                As[r][c4 * 4 + 0] = wmma::__float_to_tf32(v.x);
                As[r][c4 * 4 + 1] = wmma::__float_to_tf32(v.y);
                As[r][c4 * 4 + 2] = wmma::__float_to_tf32(v.z);
                As[r][c4 * 4 + 3] = wmma::__float_to_tf32(v.w);
            }
            #pragma unroll
            for (int i = 0; i < 4; i++) {
                int idx = t + i * 256;
                int r = idx >> 5, c4 = idx & 31;
                float4 v = *(const float4*)&W[(size_t)(kt + r) * HID_F + c4 * 4];
                Bs[r][c4 * 4 + 0] = wmma::__float_to_tf32(v.x);
                Bs[r][c4 * 4 + 1] = wmma::__float_to_tf32(v.y);
                Bs[r][c4 * 4 + 2] = wmma::__float_to_tf32(v.z);
                Bs[r][c4 * 4 + 3] = wmma::__float_to_tf32(v.w);
            }
            __syncthreads();
            #pragma unroll
            for (int kk = 0; kk < 4; kk++) {
                wmma::fragment<wmma::matrix_a, 16, 16, 8, wmma::precision::tf32, wmma::row_major> af[4];
                #pragma unroll
                for (int i = 0; i < 4; i++)
                    wmma::load_matrix_sync(af[i], &As[wm * 64 + i * 16][kk * 8], GA_PAD);
                wmma::fragment<wmma::matrix_b, 16, 16, 8, wmma::precision::tf32, wmma::row_major> bf[2];
                #pragma unroll
                for (int j = 0; j < 2; j++)
                    wmma::load_matrix_sync(bf[j], &Bs[kk * 8][wn * 32 + j * 16], GB_PAD);
                #pragma unroll
                for (int i = 0; i < 4; i++)
                    #pragma unroll
                    for (int j = 0; j < 2; j++)
                        wmma::mma_sync(acc[i][j], af[i], bf[j], acc[i][j]);
            }
            __syncthreads();
        }
    }
    // epilogue: two 64-row halves through overlaid smem C, coalesced stores
    #pragma unroll
    for (int half = 0; half < 2; half++) {
        if (wm == half) {
            #pragma unroll
            for (int i = 0; i < 4; i++)
                #pragma unroll
                for (int j = 0; j < 2; j++)
                    wmma::store_matrix_sync(&Cs[i * 16][wn * 32 + j * 16], acc[i][j],
                                            GB_PAD, wmma::mem_row_major);
        }
        __syncthreads();
        #pragma unroll
        for (int it = 0; it < 8; it++) {
            int idx = t + it * 256;
            int r = idx >> 5, c4 = idx & 31;
            int grow = brow + half * 64 + r;
            if (grow < N_NODES) {
                float4 v = *(float4*)&Cs[r][c4 * 4];
                const float4 bv = *(const float4*)&bias[c4 * 4];
                v.x = fmaxf(v.x + bv.x, 0.f);
                v.y = fmaxf(v.y + bv.y, 0.f);
                v.z = fmaxf(v.z + bv.z, 0.f);
                v.w = fmaxf(v.w + bv.w, 0.f);
                *(float4*)&g_h1[(size_t)grow * HID_F + c4 * 4] = v;
            }
        }
        __syncthreads();
    }
}

// ---------------- GEMM2 (TF32 wmma): g_s2z = [h1@W2s + b2 | h1@W2n] ----------------
__global__ void __launch_bounds__(256) k_gemm2(
    const float* __restrict__ Wa, const float* __restrict__ Wb,
    const float* __restrict__ bias)
{
    __shared__ __align__(16) char smem_raw[G_SMEM_BYTES];
    float (*As)[GA_PAD] = (float(*)[GA_PAD])smem_raw;
    float (*Bs)[GB_PAD] = (float(*)[GB_PAD])(smem_raw + 128 * GA_PAD * 4);
    float (*Cs)[GB_PAD] = (float(*)[GB_PAD])smem_raw;

    int t = threadIdx.x, warp = t >> 5;
    int wm = warp & 1, wn = warp >> 1;
    int brow = blockIdx.x * 128;

    wmma::fragment<wmma::accumulator, 16, 16, 8, float> acc[4][2];
    #pragma unroll
    for (int i = 0; i < 4; i++)
        #pragma unroll
        for (int j = 0; j < 2; j++) wmma::fill_fragment(acc[i][j], 0.f);

    for (int kt = 0; kt < HID_F; kt += 32) {
        #pragma unroll
        for (int i = 0; i < 4; i++) {
            int idx = t + i * 256;
            int r = idx >> 3, c4 = idx & 7;
            int grow = brow + r;
            float4 v = make_float4(0.f, 0.f, 0.f, 0.f);
            if (grow < N_NODES)
                v = *(const float4*)&g_h1[(size_t)grow * HID_F + kt + c4 * 4];
            As[r][c4 * 4 + 0] = wmma::__float_to_tf32(v.x);
            As[r][c4 * 4 + 1] = wmma::__float_to_tf32(v.y);
            As[r][c4 * 4 + 2] = wmma::__float_to_tf32(v.z);
            As[r][c4 * 4 + 3] = wmma::__float_to_tf32(v.w);
        }
        #pragma unroll
        for (int i = 0; i < 4; i++) {
            int idx = t + i * 256;
            int r = idx >> 5, c4 = idx & 31;
            float4 v;
            if (c4 < 16) v = *(const float4*)&Wa[(size_t)(kt + r) * OUT_F + c4 * 4];
            else         v = *(const float4*)&Wb[(size_t)(kt + r) * OUT_F + (c4 - 16) * 4];
            Bs[r][c4 * 4 + 0] = wmma::__float_to_tf32(v.x);
            Bs[r][c4 * 4 + 1] = wmma::__float_to_tf32(v.y);
            Bs[r][c4 * 4 + 2] = wmma::__float_to_tf32(v.z);
            Bs[r][c4 * 4 + 3] = wmma::__float_to_tf32(v.w);
        }
        __syncthreads();
        #pragma unroll
        for (int kk = 0; kk < 4; kk++) {
            wmma::fragment<wmma::matrix_a, 16, 16, 8, wmma::precision::tf32, wmma::row_major> af[4];
            #pragma unroll
            for (int i = 0; i < 4; i++)
                wmma::load_matrix_sync(af[i], &As[wm * 64 + i * 16][kk * 8], GA_PAD);
            wmma::fragment<wmma::matrix_b, 16, 16, 8, wmma::precision::tf32, wmma::row_major> bf[2];
            #pragma unroll
            for (int j = 0; j < 2; j++)
                wmma::load_matrix_sync(bf[j], &Bs[kk * 8][wn * 32 + j * 16], GB_PAD);
            #pragma unroll
            for (int i = 0; i < 4; i++)
                #pragma unroll
                for (int j = 0; j < 2; j++)
                    wmma::mma_sync(acc[i][j], af[i], bf[j], acc[i][j]);
        }
        __syncthreads();
    }
    // epilogue: bias on cols < OUT_F only, no relu
    #pragma unroll
    for (int half = 0; half < 2; half++) {
        if (wm == half) {
            #pragma unroll
            for (int i = 0; i < 4; i++)
                #pragma unroll
                for (int j = 0; j < 2; j++)
                    wmma::store_matrix_sync(&Cs[i * 16][wn * 32 + j * 16], acc[i][j],
                                            GB_PAD, wmma::mem_row_major);
        }
        __syncthreads();
        #pragma unroll
        for (int it = 0; it < 8; it++) {
            int idx = t + it * 256;
            int r = idx >> 5, c4 = idx & 31;
            int grow = brow + half * 64 + r;
            if (grow < N_NODES) {
                float4 v = *(float4*)&Cs[r][c4 * 4];
                if (c4 < 16) {
                    const float4 bv = *(const float4*)&bias[c4 * 4];
                    v.x += bv.x; v.y += bv.y; v.z += bv.z; v.w += bv.w;
                }
                *(float4*)&g_s2z[(size_t)grow * 128 + c4 * 4] = v;
            }
        }
        __syncthreads();
    }
}

// ---------------- final: out = S2 + seg_mean(Z[src]); half-warp per node ----------------
__global__ void __launch_bounds__(256) k_final(float* __restrict__ out) {
    int gt  = blockIdx.x * blockDim.x + threadIdx.x;
    int ghw = gt >> 4;            // half-warp id = node
    int hl  = gt & 15;            // 16 lanes x float4 = 64 cols
    if (ghw >= N_NODES) return;
    int beg = g_rowptr[ghw], end = g_rowptr[ghw + 1];
    float4 A = make_float4(0.f, 0.f, 0.f, 0.f);
    float4 B = make_float4(0.f, 0.f, 0.f, 0.f);
    int j = beg;
    for (; j + 2 <= end; j += 2) {
        float4 va = ((const float4*)&g_s2z[(size_t)g_csr[j].x     * 128 + OUT_F])[hl];
        float4 vb = ((const float4*)&g_s2z[(size_t)g_csr[j + 1].x * 128 + OUT_F])[hl];
        A.x += va.x; A.y += va.y; A.z += va.z; A.w += va.w;
        B.x += vb.x; B.y += vb.y; B.z += vb.z; B.w += vb.w;
    }
    if (j < end) {
        float4 va = ((const float4*)&g_s2z[(size_t)g_csr[j].x * 128 + OUT_F])[hl];
        A.x += va.x; A.y += va.y; A.z += va.z; A.w += va.w;
    }
    float inv = 1.f / fmaxf((float)(end - beg), 1.f);
    float4 s2 = ((const float4*)&g_s2z[(size_t)ghw * 128])[hl];
    float4 r;
    r.x = s2.x + (A.x + B.x) * inv;
    r.y = s2.y + (A.y + B.y) * inv;
    r.z = s2.z + (A.z + B.z) * inv;
    r.w = s2.w + (A.w + B.w) * inv;
    ((float4*)&out[(size_t)ghw * OUT_F])[hl] = r;
}

// ---------------- launch ----------------
extern "C" void kernel_launch(void* const* d_in, const int* in_sizes, int n_in,
                              void* d_out, int out_size)
{
    const float* nfeat = (const float*)d_in[0];
    const float* efeat = (const float*)d_in[1];
    const int*   src   = (const int*)d_in[2];
    const int*   dst   = (const int*)d_in[3];
    const float* We    = (const float*)d_in[4];
    const float* be    = (const float*)d_in[5];
    const float* W1s   = (const float*)d_in[6];
    const float* W1n   = (const float*)d_in[7];
    const float* b1    = (const float*)d_in[8];
    const float* W2s   = (const float*)d_in[9];
    const float* W2n   = (const float*)d_in[10];
    const float* b2    = (const float*)d_in[11];
    float* out = (float*)d_out;

    const int WARP_GRID = (N_NODES * 32 + 255) / 256;   // warp-per-node kernels
    const int HW_GRID   = (N_NODES * 16 + 255) / 256;   // half-warp-per-node

    void* p = nullptr;
    cudaGetSymbolAddress(&p, g_deg);
    cudaMemsetAsync(p, 0, N_NODES * sizeof(int));
    cudaGetSymbolAddress(&p, g_hsum);
    cudaMemsetAsync(p, 0, (size_t)N_NODES * IN_F * sizeof(float));

    k_deg<<<(N_EDGES + 255) / 256, 256>>>(dst);
    k_scan_blocks<<<SCAN_NB, 1024>>>();
    k_scan_top<<<1, 32>>>();
    k_scan_add<<<SCAN_NB, 1024>>>();
    k_fill<<<(N_EDGES + 255) / 256, 256>>>(src, dst);
    k_layer0_gemm<<<N_EDGES / (2 * L0_TILE), L0_THREADS>>>(nfeat, efeat, We, be);
    k_finalize0<<<(N_NODES * IN_F + 255) / 256, 256>>>(nfeat);
    k_mean96<<<WARP_GRID, 256>>>();
    k_gemm1<<<(N_NODES + 127) / 128, 256>>>(W1s, W1n, b1);
    k_gemm2<<<(N_NODES + 127) / 128, 256>>>(W2s, W2n, b2);
    k_final<<<HW_GRID, 256>>>(out);
}